// round 11
// baseline (speedup 1.0000x reference)
#include <cuda_runtime.h>
#include <cuda_bf16.h>

// x:    (b=8, t=50, f=129, c1=32, c2=32) float32
// mask: (g=8, f=129) float32
// out:  (b=8, t=50, g=8, c1=32, c2=32) float32
//
// out[b,t,g,:,:] = sum_{f in band g} x[b,t,f,:,:] / count[g]
//
// DRAM-BW-bound streaming; irreducible traffic 222.8 MB, running at
// ~6.2 TB/s effective (~77% of 8 TB/s spec) — at the sustained HBM ceiling.
// Structure = R7 winner: one CTA per (b,t, band-pair), grid 1600, shared
// ballot preamble, two sequential contiguous band loops with MLP-8 batched
// loads, lb(256,4). This round's single A/B change: __ldg (ld.global.nc,
// evict-normal) instead of __ldcs on the streaming loads.

#define N_F      129
#define N_BANDS  8
#define PIX4     256        // 32*32 pixels / 4 floats

__global__ __launch_bounds__(256, 4) void band_avg_kernel(
    const float* __restrict__ x,
    const float* __restrict__ masks,
    float* __restrict__ out)
{
    __shared__ unsigned bits[2][5];        // ballot bitmap per band
    __shared__ int   s_start[2], s_cnt[2], s_contig[2];
    __shared__ float s_inv[2];

    const int tid = threadIdx.x;
    const int bid = blockIdx.x;            // 0..1599
    const int gp  = bid & 3;               // pair id 0..3
    const int bt  = bid >> 2;              // (b,t) tile 0..399
    const int g0  = gp;
    const int g1  = (N_BANDS - 1) - gp;

    // --- parallel mask compaction for both bands (warps 0..4) ---
    const int wid = tid >> 5;
    if (wid < 5) {
        bool on0 = false, on1 = false;
        if (tid < N_F) {
            on0 = (masks[g0 * N_F + tid] > 0.5f);
            on1 = (masks[g1 * N_F + tid] > 0.5f);
        }
        unsigned b0 = __ballot_sync(0xffffffffu, on0);
        unsigned b1 = __ballot_sync(0xffffffffu, on1);
        if ((tid & 31) == 0) { bits[0][wid] = b0; bits[1][wid] = b1; }
    }
    __syncthreads();

    if (tid < 2) {
        int total = 0, first = -1, last = -1;
        #pragma unroll
        for (int w = 0; w < 5; ++w) {
            unsigned b = bits[tid][w];
            total += __popc(b);
            if (b) {
                if (first < 0) first = w * 32 + __ffs(b) - 1;
                last = w * 32 + 31 - __clz(b);
            }
        }
        s_start[tid]  = first;
        s_cnt[tid]    = total;
        s_contig[tid] = (last - first + 1 == total) ? 1 : 0;
        s_inv[tid]    = 1.0f / (float)total;
    }
    __syncthreads();

    const float4* __restrict__ xin =
        reinterpret_cast<const float4*>(x) + ((size_t)bt * (N_F * PIX4) + tid);
    float4* __restrict__ o4 =
        reinterpret_cast<float4*>(out) + ((size_t)bt * (N_BANDS * PIX4) + tid);

    #pragma unroll 1
    for (int s = 0; s < 2; ++s) {
        const int   g     = s ? g1 : g0;
        const int   start = s_start[s];
        const int   c     = s_cnt[s];
        const float inv   = s_inv[s];

        float ax = 0.0f, ay = 0.0f, az = 0.0f, aw = 0.0f;
        float bx = 0.0f, by = 0.0f, bz = 0.0f, bw = 0.0f;

        if (s_contig[s]) {
            const float4* __restrict__ p = xin + (size_t)start * PIX4;
            // main loop: 8 independent loads in flight per thread
            int k = 0;
            #pragma unroll 1
            for (; k + 8 <= c; k += 8) {
                float4 v0 = __ldg(&p[(size_t)(k + 0) * PIX4]);
                float4 v1 = __ldg(&p[(size_t)(k + 1) * PIX4]);
                float4 v2 = __ldg(&p[(size_t)(k + 2) * PIX4]);
                float4 v3 = __ldg(&p[(size_t)(k + 3) * PIX4]);
                float4 v4 = __ldg(&p[(size_t)(k + 4) * PIX4]);
                float4 v5 = __ldg(&p[(size_t)(k + 5) * PIX4]);
                float4 v6 = __ldg(&p[(size_t)(k + 6) * PIX4]);
                float4 v7 = __ldg(&p[(size_t)(k + 7) * PIX4]);
                ax += v0.x; ay += v0.y; az += v0.z; aw += v0.w;
                bx += v1.x; by += v1.y; bz += v1.z; bw += v1.w;
                ax += v2.x; ay += v2.y; az += v2.z; aw += v2.w;
                bx += v3.x; by += v3.y; bz += v3.z; bw += v3.w;
                ax += v4.x; ay += v4.y; az += v4.z; aw += v4.w;
                bx += v5.x; by += v5.y; bz += v5.z; bw += v5.w;
                ax += v6.x; ay += v6.y; az += v6.z; aw += v6.w;
                bx += v7.x; by += v7.y; bz += v7.z; bw += v7.w;
            }
            #pragma unroll 4
            for (; k < c; ++k) {
                float4 v = __ldg(&p[(size_t)k * PIX4]);
                ax += v.x; ay += v.y; az += v.z; aw += v.w;
            }
        } else {
            // generic fallback: iterate the bitmap (unused for reference mask)
            #pragma unroll 1
            for (int f = 0; f < N_F; ++f) {
                if ((bits[s][f >> 5] >> (f & 31)) & 1u) {
                    float4 v = __ldg(&xin[(size_t)f * PIX4]);
                    ax += v.x; ay += v.y; az += v.z; aw += v.w;
                }
            }
        }

        float4 r;
        r.x = (ax + bx) * inv;
        r.y = (ay + by) * inv;
        r.z = (az + bz) * inv;
        r.w = (aw + bw) * inv;
        o4[(size_t)g * PIX4] = r;
    }
}

extern "C" void kernel_launch(void* const* d_in, const int* in_sizes, int n_in,
                              void* d_out, int out_size)
{
    const float* x     = (const float*)d_in[0];
    const float* masks = (const float*)d_in[1];
    if (n_in >= 2 && in_sizes[0] < in_sizes[1]) {
        x     = (const float*)d_in[1];
        masks = (const float*)d_in[0];
    }
    float* out = (float*)d_out;

    const int n_blocks = 8 * 50 * (N_BANDS / 2);  // 1600: one per (b,t,pair)
    band_avg_kernel<<<n_blocks, 256>>>(x, masks, out);
}

// round 12
// speedup vs baseline: 1.0518x; 1.0518x over previous
#include <cuda_runtime.h>
#include <cuda_bf16.h>

// x:    (b=8, t=50, f=129, c1=32, c2=32) float32
// mask: (g=8, f=129) float32
// out:  (b=8, t=50, g=8, c1=32, c2=32) float32
//
// out[b,t,g,:,:] = sum_{f in band g} x[b,t,f,:,:] / count[g]
//
// CONVERGED KERNEL (R7 config). DRAM-BW-bound streaming: 222.8 MB irreducible
// traffic at the measured ~6.0 TB/s sustained HBM rate -> ~36 us floor.
// Full sweep (CTA layout, occupancy, MLP, band fusion, preamble style, L2
// load/store policies) showed a flat response surface with this config at
// the optimum: one CTA per (b,t, band-pair), grid 1600, shared-memory ballot
// preamble, two sequential contiguous band loops with 8 independent float4
// loads in flight per thread, launch_bounds(256,4).

#define N_F      129
#define N_BANDS  8
#define PIX4     256        // 32*32 pixels / 4 floats

__global__ __launch_bounds__(256, 4) void band_avg_kernel(
    const float* __restrict__ x,
    const float* __restrict__ masks,
    float* __restrict__ out)
{
    __shared__ unsigned bits[2][5];        // ballot bitmap per band
    __shared__ int   s_start[2], s_cnt[2], s_contig[2];
    __shared__ float s_inv[2];

    const int tid = threadIdx.x;
    const int bid = blockIdx.x;            // 0..1599
    const int gp  = bid & 3;               // pair id 0..3
    const int bt  = bid >> 2;              // (b,t) tile 0..399
    const int g0  = gp;
    const int g1  = (N_BANDS - 1) - gp;

    // --- parallel mask compaction for both bands (warps 0..4) ---
    const int wid = tid >> 5;
    if (wid < 5) {
        bool on0 = false, on1 = false;
        if (tid < N_F) {
            on0 = (masks[g0 * N_F + tid] > 0.5f);
            on1 = (masks[g1 * N_F + tid] > 0.5f);
        }
        unsigned b0 = __ballot_sync(0xffffffffu, on0);
        unsigned b1 = __ballot_sync(0xffffffffu, on1);
        if ((tid & 31) == 0) { bits[0][wid] = b0; bits[1][wid] = b1; }
    }
    __syncthreads();

    if (tid < 2) {
        int total = 0, first = -1, last = -1;
        #pragma unroll
        for (int w = 0; w < 5; ++w) {
            unsigned b = bits[tid][w];
            total += __popc(b);
            if (b) {
                if (first < 0) first = w * 32 + __ffs(b) - 1;
                last = w * 32 + 31 - __clz(b);
            }
        }
        s_start[tid]  = first;
        s_cnt[tid]    = total;
        s_contig[tid] = (last - first + 1 == total) ? 1 : 0;
        s_inv[tid]    = 1.0f / (float)total;
    }
    __syncthreads();

    const float4* __restrict__ xin =
        reinterpret_cast<const float4*>(x) + ((size_t)bt * (N_F * PIX4) + tid);
    float4* __restrict__ o4 =
        reinterpret_cast<float4*>(out) + ((size_t)bt * (N_BANDS * PIX4) + tid);

    #pragma unroll 1
    for (int s = 0; s < 2; ++s) {
        const int   g     = s ? g1 : g0;
        const int   start = s_start[s];
        const int   c     = s_cnt[s];
        const float inv   = s_inv[s];

        float ax = 0.0f, ay = 0.0f, az = 0.0f, aw = 0.0f;
        float bx = 0.0f, by = 0.0f, bz = 0.0f, bw = 0.0f;

        if (s_contig[s]) {
            const float4* __restrict__ p = xin + (size_t)start * PIX4;
            // main loop: 8 independent loads in flight per thread
            int k = 0;
            #pragma unroll 1
            for (; k + 8 <= c; k += 8) {
                float4 v0 = __ldcs(&p[(size_t)(k + 0) * PIX4]);
                float4 v1 = __ldcs(&p[(size_t)(k + 1) * PIX4]);
                float4 v2 = __ldcs(&p[(size_t)(k + 2) * PIX4]);
                float4 v3 = __ldcs(&p[(size_t)(k + 3) * PIX4]);
                float4 v4 = __ldcs(&p[(size_t)(k + 4) * PIX4]);
                float4 v5 = __ldcs(&p[(size_t)(k + 5) * PIX4]);
                float4 v6 = __ldcs(&p[(size_t)(k + 6) * PIX4]);
                float4 v7 = __ldcs(&p[(size_t)(k + 7) * PIX4]);
                ax += v0.x; ay += v0.y; az += v0.z; aw += v0.w;
                bx += v1.x; by += v1.y; bz += v1.z; bw += v1.w;
                ax += v2.x; ay += v2.y; az += v2.z; aw += v2.w;
                bx += v3.x; by += v3.y; bz += v3.z; bw += v3.w;
                ax += v4.x; ay += v4.y; az += v4.z; aw += v4.w;
                bx += v5.x; by += v5.y; bz += v5.z; bw += v5.w;
                ax += v6.x; ay += v6.y; az += v6.z; aw += v6.w;
                bx += v7.x; by += v7.y; bz += v7.z; bw += v7.w;
            }
            #pragma unroll 4
            for (; k < c; ++k) {
                float4 v = __ldcs(&p[(size_t)k * PIX4]);
                ax += v.x; ay += v.y; az += v.z; aw += v.w;
            }
        } else {
            // generic fallback: iterate the bitmap (unused for reference mask)
            #pragma unroll 1
            for (int f = 0; f < N_F; ++f) {
                if ((bits[s][f >> 5] >> (f & 31)) & 1u) {
                    float4 v = __ldcs(&xin[(size_t)f * PIX4]);
                    ax += v.x; ay += v.y; az += v.z; aw += v.w;
                }
            }
        }

        float4 r;
        r.x = (ax + bx) * inv;
        r.y = (ay + by) * inv;
        r.z = (az + bz) * inv;
        r.w = (aw + bw) * inv;
        o4[(size_t)g * PIX4] = r;
    }
}

extern "C" void kernel_launch(void* const* d_in, const int* in_sizes, int n_in,
                              void* d_out, int out_size)
{
    const float* x     = (const float*)d_in[0];
    const float* masks = (const float*)d_in[1];
    if (n_in >= 2 && in_sizes[0] < in_sizes[1]) {
        x     = (const float*)d_in[1];
        masks = (const float*)d_in[0];
    }
    float* out = (float*)d_out;

    const int n_blocks = 8 * 50 * (N_BANDS / 2);  // 1600: one per (b,t,pair)
    band_avg_kernel<<<n_blocks, 256>>>(x, masks, out);
}